// round 12
// baseline (speedup 1.0000x reference)
#include <cuda_runtime.h>
#include <cuda_fp16.h>

// ---------------- problem constants ----------------
namespace {
constexpr int N_MOL  = 131072;
constexpr int E_MOL  = 524288;
constexpr int NG     = 4096;
constexpr int D_MOL  = 6;
constexpr int N_PROT = 100000;
constexpr int E_PROT = 1600000;
constexpr int D_PROT = 20;
constexpr int HD     = 64;
}

// ---------------- scratch (device globals; no allocation allowed) ----------------
__device__ __align__(256) __half g_mA[N_MOL * HD];
__device__ __align__(256) __half g_pA[N_PROT * HD];
__device__ __align__(256) float g_mB[N_MOL * HD];
__device__ __align__(256) float g_pB[N_PROT * HD];
__device__ int g_mcnt[N_MOL];
__device__ int g_moff[N_MOL + 1];
__device__ int g_mcur[N_MOL];
__device__ int g_msrc[E_MOL];
__device__ int g_pcnt[N_PROT];
__device__ int g_poff[N_PROT + 1];
__device__ int g_pcur[N_PROT];
__device__ int g_psrc[E_PROT];
__device__ int g_part[256];
__device__ int g_part2[256];
__device__ float g_dinv[N_MOL];
__device__ float g_hs[N_PROT];
__device__ float g_hd[N_PROT];
__device__ __align__(256) float g_molf[NG * HD];
__device__ float g_gcnt[NG];
__device__ float g_protf[HD];

// ---------------- helpers ----------------
__device__ __forceinline__ float leaky02(float x) { return x > 0.f ? x : 0.2f * x; }

__device__ __forceinline__ void red4(float* a, float x, float y, float z, float w) {
    asm volatile("red.global.add.v4.f32 [%0], {%1,%2,%3,%4};"
                 :: "l"(a), "f"(x), "f"(y), "f"(z), "f"(w) : "memory");
}

// load 8 consecutive halfs (16B, LDG.128) -> two float4
__device__ __forceinline__ void ldh8(const __half* p, float4& lo, float4& hi) {
    uint4 raw = *(const uint4*)p;
    float2 f0 = __half22float2(*reinterpret_cast<__half2*>(&raw.x));
    float2 f1 = __half22float2(*reinterpret_cast<__half2*>(&raw.y));
    float2 f2 = __half22float2(*reinterpret_cast<__half2*>(&raw.z));
    float2 f3 = __half22float2(*reinterpret_cast<__half2*>(&raw.w));
    lo = make_float4(f0.x, f0.y, f1.x, f1.y);
    hi = make_float4(f2.x, f2.y, f3.x, f3.y);
}

// ---------------- setup kernels ----------------
__global__ void k_init() {
    int i = blockIdx.x * blockDim.x + threadIdx.x;   // covers 262144
    if (i < NG * HD) g_molf[i] = 0.f;
    if (i < NG)      g_gcnt[i] = 0.f;
    if (i < HD)      g_protf[i] = 0.f;
    if (i < N_MOL)   g_mcnt[i] = 0;
    if (i < N_PROT)  g_pcnt[i] = 0;
}

__global__ void k_hist(const int* __restrict__ dst, int* __restrict__ cnt, int E) {
    int e = blockIdx.x * blockDim.x + threadIdx.x;
    if (e < E) atomicAdd(&cnt[dst[e]], 1);
}

__global__ void k_scan1(const int* __restrict__ cnt, int* __restrict__ off,
                        int* __restrict__ part, int n) {
    __shared__ int wsum[8];
    int t = threadIdx.x;
    int base = blockIdx.x * 1024 + t * 4;
    int v0 = 0, v1 = 0, v2 = 0, v3 = 0;
    if (base + 3 < n) {
        int4 v = *(const int4*)&cnt[base];
        v0 = v.x; v1 = v.y; v2 = v.z; v3 = v.w;
    } else {
        if (base + 0 < n) v0 = cnt[base + 0];
        if (base + 1 < n) v1 = cnt[base + 1];
        if (base + 2 < n) v2 = cnt[base + 2];
        if (base + 3 < n) v3 = cnt[base + 3];
    }
    int s = v0 + v1 + v2 + v3;
    int lane = t & 31, w = t >> 5;
    int inc = s;
#pragma unroll
    for (int o = 1; o < 32; o <<= 1) {
        int x = __shfl_up_sync(0xffffffffu, inc, o);
        if (lane >= o) inc += x;
    }
    if (lane == 31) wsum[w] = inc;
    __syncthreads();
    int wbase = 0;
    for (int i = 0; i < w; i++) wbase += wsum[i];
    int ex = wbase + inc - s;
    if (base + 0 < n) off[base + 0] = ex;
    if (base + 1 < n) off[base + 1] = ex + v0;
    if (base + 2 < n) off[base + 2] = ex + v0 + v1;
    if (base + 3 < n) off[base + 3] = ex + v0 + v1 + v2;
    if (t == 255) part[blockIdx.x] = wbase + inc;
}

__global__ void k_scan_tot(int* __restrict__ part, int nb) {
    __shared__ int ws[4];
    int t = threadIdx.x;                 // 128 threads
    int v = (t < nb) ? part[t] : 0;
    int lane = t & 31, w = t >> 5;
    int inc = v;
#pragma unroll
    for (int o = 1; o < 32; o <<= 1) {
        int x = __shfl_up_sync(0xffffffffu, inc, o);
        if (lane >= o) inc += x;
    }
    if (lane == 31) ws[w] = inc;
    __syncthreads();
    int wbase = 0;
    for (int i = 0; i < w; i++) wbase += ws[i];
    if (t < nb) part[t] = wbase + inc - v;
}

__global__ void k_scan_add(int* __restrict__ off, const int* __restrict__ part,
                           int* __restrict__ cur, int n, int e_total) {
    int i = blockIdx.x * blockDim.x + threadIdx.x;
    if (i < n) {
        int o = off[i] + part[i >> 10];
        off[i] = o;
        cur[i] = o;
    }
    if (i == 0) off[n] = e_total;
}

__global__ void k_fill(const int* __restrict__ src, const int* __restrict__ dst,
                       int* __restrict__ cur, int* __restrict__ srcs, int E) {
    int e = blockIdx.x * blockDim.x + threadIdx.x;
    if (e < E) {
        int slot = atomicAdd(&cur[dst[e]], 1);
        srcs[slot] = src[e];
    }
}

__global__ void k_dinv() {
    int i = blockIdx.x * blockDim.x + threadIdx.x;
    if (i < N_MOL) g_dinv[i] = rsqrtf((float)(g_mcnt[i] + 1));
}

// ---------------- dense matvec (fp32 in, fp16 out) ----------------
template <int DIN, bool RELU_IN>
__global__ void k_matvec(const float* __restrict__ in, const float* __restrict__ W,
                         __half* __restrict__ out, int n) {
    const int lane = threadIdx.x & 31;
    const int warp = threadIdx.x >> 5;
    const int j = ((warp & 1) << 5) | lane;
    float wreg[DIN];
#pragma unroll
    for (int k = 0; k < DIN; ++k) wreg[k] = __ldg(&W[k * HD + j]);
    const int step = gridDim.x * 4;
    for (int node = blockIdx.x * 4 + (warp >> 1); node < n; node += step) {
        const float* row = in + (size_t)node * DIN;
        float r0 = 0.f, r1 = 0.f;
        if (DIN >= 32) {
            r0 = row[lane];
            if (DIN > 32 && lane + 32 < DIN) r1 = row[lane + 32];
        } else if (lane < DIN) {
            r0 = row[lane];
        }
        if (RELU_IN) { r0 = fmaxf(r0, 0.f); r1 = fmaxf(r1, 0.f); }
        float acc = 0.f;
#pragma unroll
        for (int k = 0; k < DIN; ++k) {
            float a = __shfl_sync(0xffffffffu, (k < 32) ? r0 : r1, k & 31);
            acc = fmaf(a, wreg[k], acc);
        }
        out[(size_t)node * HD + j] = __float2half_rn(acc);
    }
}

// ---------------- GCN accumulate (warp per dst node; 16B loads, 4 edges in flight) ----------------
template <bool POOL>
__global__ void k_gcn_acc(const __half* __restrict__ h, float* __restrict__ out,
                          const float* __restrict__ bias, const int* __restrict__ batch) {
    int wid = (blockIdx.x * blockDim.x + threadIdx.x) >> 5;
    if (wid >= N_MOL) return;
    int lane = threadIdx.x & 31;
    int q = lane >> 3;            // quarter 0..3
    int c8 = (lane & 7) << 3;     // column base (8 halfs per lane)
    int beg = g_moff[wid], end = g_moff[wid + 1];
    float dd = g_dinv[wid];
    float4 alo = {0.f,0.f,0.f,0.f}, ahi = {0.f,0.f,0.f,0.f};
    if (q == 0) {
        float cs = dd * dd;
        float4 lo, hi;
        ldh8(&h[(size_t)wid * HD + c8], lo, hi);
        alo.x = cs*lo.x; alo.y = cs*lo.y; alo.z = cs*lo.z; alo.w = cs*lo.w;
        ahi.x = cs*hi.x; ahi.y = cs*hi.y; ahi.z = cs*hi.z; ahi.w = cs*hi.w;
    }
    for (int base = beg; base < end; base += 32) {
        int nn = min(32, end - base);
        int s = (lane < nn) ? g_msrc[base + lane] : 0;
        float cf = (lane < nn) ? g_dinv[s] * dd : 0.f;
#pragma unroll 2
        for (int k = 0; k < nn; k += 4) {
            int idx = k + q;
            int sk = __shfl_sync(0xffffffffu, s, idx);
            float ck = __shfl_sync(0xffffffffu, cf, idx);
            if (idx < nn) {
                float4 lo, hi;
                ldh8(&h[(size_t)sk * HD + c8], lo, hi);
                alo.x = fmaf(ck, lo.x, alo.x); alo.y = fmaf(ck, lo.y, alo.y);
                alo.z = fmaf(ck, lo.z, alo.z); alo.w = fmaf(ck, lo.w, alo.w);
                ahi.x = fmaf(ck, hi.x, ahi.x); ahi.y = fmaf(ck, hi.y, ahi.y);
                ahi.z = fmaf(ck, hi.z, ahi.z); ahi.w = fmaf(ck, hi.w, ahi.w);
            }
        }
    }
#pragma unroll
    for (int o = 8; o <= 16; o <<= 1) {
        alo.x += __shfl_xor_sync(0xffffffffu, alo.x, o);
        alo.y += __shfl_xor_sync(0xffffffffu, alo.y, o);
        alo.z += __shfl_xor_sync(0xffffffffu, alo.z, o);
        alo.w += __shfl_xor_sync(0xffffffffu, alo.w, o);
        ahi.x += __shfl_xor_sync(0xffffffffu, ahi.x, o);
        ahi.y += __shfl_xor_sync(0xffffffffu, ahi.y, o);
        ahi.z += __shfl_xor_sync(0xffffffffu, ahi.z, o);
        ahi.w += __shfl_xor_sync(0xffffffffu, ahi.w, o);
    }
    if (lane < 8) {
        float4 b0 = *(const float4*)&bias[c8];
        float4 b1 = *(const float4*)&bias[c8 + 4];
        alo.x += b0.x; alo.y += b0.y; alo.z += b0.z; alo.w += b0.w;
        ahi.x += b1.x; ahi.y += b1.y; ahi.z += b1.z; ahi.w += b1.w;
        if (POOL) {
            int g = batch[wid];
            red4(&g_molf[(size_t)g * HD + c8],     alo.x, alo.y, alo.z, alo.w);
            red4(&g_molf[(size_t)g * HD + c8 + 4], ahi.x, ahi.y, ahi.z, ahi.w);
            if (lane == 0) atomicAdd(&g_gcnt[g], 1.f);
        } else {
            *(float4*)&out[(size_t)wid * HD + c8]     = alo;
            *(float4*)&out[(size_t)wid * HD + c8 + 4] = ahi;
        }
    }
}

// ---------------- GAT per-node attention scalars (fp16 input) ----------------
__global__ void k_att(const __half* __restrict__ h, const float* __restrict__ asrc,
                      const float* __restrict__ adst) {
    int wid = (blockIdx.x * blockDim.x + threadIdx.x) >> 5;
    int lane = threadIdx.x & 31;
    if (wid >= N_PROT) return;
    float h0 = __half2float(h[(size_t)wid * HD + lane]);
    float h1 = __half2float(h[(size_t)wid * HD + lane + 32]);
    float s = h0 * __ldg(&asrc[lane]) + h1 * __ldg(&asrc[lane + 32]);
    float d = h0 * __ldg(&adst[lane]) + h1 * __ldg(&adst[lane + 32]);
#pragma unroll
    for (int o = 16; o; o >>= 1) {
        s += __shfl_xor_sync(0xffffffffu, s, o);
        d += __shfl_xor_sync(0xffffffffu, d, o);
    }
    if (lane == 0) { g_hs[wid] = s; g_hd[wid] = d; }
}

// ---------------- GAT accumulate (warp per dst node; single-pass softmax; 16B loads) ----------------
template <bool RELU_OUT>
__global__ void k_gat_acc(const __half* __restrict__ h, float* __restrict__ out,
                          const float* __restrict__ bias) {
    int wid = (blockIdx.x * blockDim.x + threadIdx.x) >> 5;
    if (wid >= N_PROT) return;
    int lane = threadIdx.x & 31;
    int q = lane >> 3;
    int c8 = (lane & 7) << 3;
    int beg = g_poff[wid], end = g_poff[wid + 1];
    float hdv = g_hd[wid];
    float wself = __expf(leaky02(g_hs[wid] + hdv));
    float ssum = (lane == 0) ? wself : 0.f;
    float4 alo = {0.f,0.f,0.f,0.f}, ahi = {0.f,0.f,0.f,0.f};
    if (q == 0) {
        float4 lo, hi;
        ldh8(&h[(size_t)wid * HD + c8], lo, hi);
        alo.x = wself*lo.x; alo.y = wself*lo.y; alo.z = wself*lo.z; alo.w = wself*lo.w;
        ahi.x = wself*hi.x; ahi.y = wself*hi.y; ahi.z = wself*hi.z; ahi.w = wself*hi.w;
    }
    for (int base = beg; base < end; base += 32) {
        int nn = min(32, end - base);
        int s = (lane < nn) ? g_psrc[base + lane] : 0;
        float wgt = (lane < nn) ? __expf(leaky02(g_hs[s] + hdv)) : 0.f;
        ssum += wgt;
#pragma unroll 2
        for (int k = 0; k < nn; k += 4) {
            int idx = k + q;
            int sk = __shfl_sync(0xffffffffu, s, idx);
            float wk = __shfl_sync(0xffffffffu, wgt, idx);
            if (idx < nn) {
                float4 lo, hi;
                ldh8(&h[(size_t)sk * HD + c8], lo, hi);
                alo.x = fmaf(wk, lo.x, alo.x); alo.y = fmaf(wk, lo.y, alo.y);
                alo.z = fmaf(wk, lo.z, alo.z); alo.w = fmaf(wk, lo.w, alo.w);
                ahi.x = fmaf(wk, hi.x, ahi.x); ahi.y = fmaf(wk, hi.y, ahi.y);
                ahi.z = fmaf(wk, hi.z, ahi.z); ahi.w = fmaf(wk, hi.w, ahi.w);
            }
        }
    }
#pragma unroll
    for (int o = 8; o <= 16; o <<= 1) {
        alo.x += __shfl_xor_sync(0xffffffffu, alo.x, o);
        alo.y += __shfl_xor_sync(0xffffffffu, alo.y, o);
        alo.z += __shfl_xor_sync(0xffffffffu, alo.z, o);
        alo.w += __shfl_xor_sync(0xffffffffu, alo.w, o);
        ahi.x += __shfl_xor_sync(0xffffffffu, ahi.x, o);
        ahi.y += __shfl_xor_sync(0xffffffffu, ahi.y, o);
        ahi.z += __shfl_xor_sync(0xffffffffu, ahi.z, o);
        ahi.w += __shfl_xor_sync(0xffffffffu, ahi.w, o);
    }
#pragma unroll
    for (int o = 16; o; o >>= 1)
        ssum += __shfl_xor_sync(0xffffffffu, ssum, o);
    if (lane < 8) {
        float inv = 1.f / ssum;
        float4 b0 = *(const float4*)&bias[c8];
        float4 b1 = *(const float4*)&bias[c8 + 4];
        float4 v0, v1;
        v0.x = fmaf(alo.x, inv, b0.x); v0.y = fmaf(alo.y, inv, b0.y);
        v0.z = fmaf(alo.z, inv, b0.z); v0.w = fmaf(alo.w, inv, b0.w);
        v1.x = fmaf(ahi.x, inv, b1.x); v1.y = fmaf(ahi.y, inv, b1.y);
        v1.z = fmaf(ahi.z, inv, b1.z); v1.w = fmaf(ahi.w, inv, b1.w);
        if (RELU_OUT) {
            v0.x = fmaxf(v0.x, 0.f); v0.y = fmaxf(v0.y, 0.f);
            v0.z = fmaxf(v0.z, 0.f); v0.w = fmaxf(v0.w, 0.f);
            v1.x = fmaxf(v1.x, 0.f); v1.y = fmaxf(v1.y, 0.f);
            v1.z = fmaxf(v1.z, 0.f); v1.w = fmaxf(v1.w, 0.f);
        }
        *(float4*)&out[(size_t)wid * HD + c8]     = v0;
        *(float4*)&out[(size_t)wid * HD + c8 + 4] = v1;
    }
}

// ---------------- pooling + classifier ----------------
__global__ void k_prot_pool(const float* __restrict__ h) {
    int j = threadIdx.x;  // 64
    float s = 0.f;
    for (int i = blockIdx.x; i < N_PROT; i += gridDim.x)
        s += h[(size_t)i * HD + j];
    atomicAdd(&g_protf[j], s);
}

__global__ void k_cls(const float* __restrict__ w1, const float* __restrict__ b1,
                      const float* __restrict__ w2, const float* __restrict__ b2,
                      float* __restrict__ out) {
    int g = blockIdx.x;
    int j = threadIdx.x;
    __shared__ float fused[2 * HD];
    __shared__ float red[2];
    float cnt = fmaxf(g_gcnt[g], 1.f);
    fused[j] = g_molf[(size_t)g * HD + j] / cnt;
    fused[HD + j] = g_protf[j] * (1.f / (float)N_PROT);
    __syncthreads();
    float z = __ldg(&b1[j]);
#pragma unroll
    for (int k = 0; k < 2 * HD; ++k)
        z = fmaf(fused[k], __ldg(&w1[k * HD + j]), z);
    z = fmaxf(z, 0.f);
    float t = z * __ldg(&w2[j]);
#pragma unroll
    for (int o = 16; o; o >>= 1) t += __shfl_xor_sync(0xffffffffu, t, o);
    if ((j & 31) == 0) red[j >> 5] = t;
    __syncthreads();
    if (j == 0)
        out[g] = 1.f / (1.f + expf(-(red[0] + red[1] + __ldg(&b2[0]))));
}

// ---------------- launch ----------------
extern "C" void kernel_launch(void* const* d_in, const int* in_sizes, int n_in,
                              void* d_out, int out_size) {
    const float* mol_x  = (const float*)d_in[0];
    const int*   mei    = (const int*)  d_in[1];
    const int*   mbatch = (const int*)  d_in[2];
    const float* prot_x = (const float*)d_in[3];
    const int*   pei    = (const int*)  d_in[4];
    const float* gw1 = (const float*)d_in[5];
    const float* gb1 = (const float*)d_in[6];
    const float* gw2 = (const float*)d_in[7];
    const float* gb2 = (const float*)d_in[8];
    const float* aw1 = (const float*)d_in[9];
    const float* as1 = (const float*)d_in[10];
    const float* ad1 = (const float*)d_in[11];
    const float* ab1 = (const float*)d_in[12];
    const float* aw2 = (const float*)d_in[13];
    const float* as2 = (const float*)d_in[14];
    const float* ad2 = (const float*)d_in[15];
    const float* ab2 = (const float*)d_in[16];
    const float* cw1 = (const float*)d_in[17];
    const float* cb1 = (const float*)d_in[18];
    const float* cw2 = (const float*)d_in[19];
    const float* cb2 = (const float*)d_in[20];
    float* out = (float*)d_out;

    __half *mA, *pA;
    float *mB, *pB;
    cudaGetSymbolAddress((void**)&mA, g_mA);
    cudaGetSymbolAddress((void**)&mB, g_mB);
    cudaGetSymbolAddress((void**)&pA, g_pA);
    cudaGetSymbolAddress((void**)&pB, g_pB);
    int *mcnt, *moff, *mcur, *msrcs, *pcnt, *poff, *pcur, *psrcs, *part, *part2;
    cudaGetSymbolAddress((void**)&mcnt, g_mcnt);
    cudaGetSymbolAddress((void**)&moff, g_moff);
    cudaGetSymbolAddress((void**)&mcur, g_mcur);
    cudaGetSymbolAddress((void**)&msrcs, g_msrc);
    cudaGetSymbolAddress((void**)&pcnt, g_pcnt);
    cudaGetSymbolAddress((void**)&poff, g_poff);
    cudaGetSymbolAddress((void**)&pcur, g_pcur);
    cudaGetSymbolAddress((void**)&psrcs, g_psrc);
    cudaGetSymbolAddress((void**)&part, g_part);
    cudaGetSymbolAddress((void**)&part2, g_part2);

    const int* msrc = mei;
    const int* mdst = mei + E_MOL;
    const int* psrc = pei;
    const int* pdst = pei + E_PROT;

    // persistent streams + events (created once; not device allocations)
    static cudaStream_t s_prot = nullptr, s_pmv = nullptr;
    static cudaEvent_t ev_fork = nullptr, ev_join = nullptr, ev_pmv = nullptr;
    if (s_prot == nullptr) {
        cudaStreamCreateWithFlags(&s_prot, cudaStreamNonBlocking);
        cudaStreamCreateWithFlags(&s_pmv, cudaStreamNonBlocking);
        cudaEventCreateWithFlags(&ev_fork, cudaEventDisableTiming);
        cudaEventCreateWithFlags(&ev_join, cudaEventDisableTiming);
        cudaEventCreateWithFlags(&ev_pmv, cudaEventDisableTiming);
    }

    const int T = 256;
    k_init<<<(NG * HD + T - 1) / T, T>>>();

    // ---- fork ----
    cudaEventRecord(ev_fork, 0);
    cudaStreamWaitEvent(s_prot, ev_fork, 0);
    cudaStreamWaitEvent(s_pmv, ev_fork, 0);

    // prot CSR build (s_prot)  ||  prot matvec1 + att1 (s_pmv)
    k_hist<<<(E_PROT + T - 1) / T, T, 0, s_prot>>>(pdst, pcnt, E_PROT);
    k_scan1<<<(N_PROT + 1023) / 1024, 256, 0, s_prot>>>(pcnt, poff, part2, N_PROT);
    k_scan_tot<<<1, 128, 0, s_prot>>>(part2, (N_PROT + 1023) / 1024);
    k_scan_add<<<(N_PROT + T - 1) / T, T, 0, s_prot>>>(poff, part2, pcur, N_PROT, E_PROT);
    k_fill<<<(E_PROT + T - 1) / T, T, 0, s_prot>>>(psrc, pdst, pcur, psrcs, E_PROT);

    k_matvec<D_PROT, false><<<2048, T, 0, s_pmv>>>(prot_x, aw1, pA, N_PROT);
    k_att<<<(N_PROT * 32 + T - 1) / T, T, 0, s_pmv>>>(pA, as1, ad1);
    cudaEventRecord(ev_pmv, s_pmv);
    cudaStreamWaitEvent(s_prot, ev_pmv, 0);

    // prot GAT chain (s_prot)
    k_gat_acc<true><<<(N_PROT + 7) / 8, T, 0, s_prot>>>(pA, pB, ab1);
    k_matvec<HD, false><<<2048, T, 0, s_prot>>>(pB, aw2, pA, N_PROT);
    k_att<<<(N_PROT * 32 + T - 1) / T, T, 0, s_prot>>>(pA, as2, ad2);
    k_gat_acc<false><<<(N_PROT + 7) / 8, T, 0, s_prot>>>(pA, pB, ab2);
    k_prot_pool<<<512, 64, 0, s_prot>>>(pB);
    cudaEventRecord(ev_join, s_prot);

    // ---- mol branch on main (capture) stream ----
    k_hist<<<(E_MOL + T - 1) / T, T>>>(mdst, mcnt, E_MOL);
    k_scan1<<<(N_MOL + 1023) / 1024, 256>>>(mcnt, moff, part, N_MOL);
    k_scan_tot<<<1, 128>>>(part, (N_MOL + 1023) / 1024);
    k_scan_add<<<(N_MOL + T - 1) / T, T>>>(moff, part, mcur, N_MOL, E_MOL);
    k_fill<<<(E_MOL + T - 1) / T, T>>>(msrc, mdst, mcur, msrcs, E_MOL);
    k_dinv<<<(N_MOL + T - 1) / T, T>>>();
    k_matvec<D_MOL, false><<<2048, T>>>(mol_x, gw1, mA, N_MOL);
    k_gcn_acc<false><<<(N_MOL + 7) / 8, T>>>(mA, mB, gb1, nullptr);
    k_matvec<HD, true><<<2048, T>>>(mB, gw2, mA, N_MOL);
    k_gcn_acc<true><<<(N_MOL + 7) / 8, T>>>(mA, nullptr, gb2, mbatch);   // fused pool

    // ---- join + classifier ----
    cudaStreamWaitEvent(0, ev_join, 0);
    k_cls<<<NG, HD>>>(cw1, cb1, cw2, cb2, out);
}